// round 6
// baseline (speedup 1.0000x reference)
#include <cuda_runtime.h>
#include <cuda_bf16.h>

#define BATCH    16
#define TDIM     1024
#define DDIM     1024
#define RADIUS   15
#define NBLOCKS  2048
#define ROW_TOTAL (64 * BATCH * 5)   // hits per g-row: 64 timesteps x 16 batches x top-5

// Per-output-group histogram of top-5 index hits; g = t >> 6.
// Zero at load; epilogue re-zeroes after reading -> invariant holds per replay.
__device__ int g_counts[BATCH * DDIM];
__device__ int g_done;               // completion ticket counter (reset by last ticket)

// Monotone float->unsigned bit mapping (order-preserving for non-NaN).
__device__ __forceinline__ unsigned sortable(float f) {
    unsigned u = __float_as_uint(f);
    return u ^ (((unsigned)((int)u >> 31)) | 0x80000000u);
}
__device__ __forceinline__ float unsortable(unsigned s) {
    unsigned u = (s & 0x80000000u) ? (s ^ 0x80000000u) : ~s;
    return __uint_as_float(u);
}
__device__ __forceinline__ float comp4(float4 v, int j) {
    return (j == 0) ? v.x : (j == 1) ? v.y : (j == 2) ? v.z : v.w;
}

// One warp per (b,t) row of 1024 floats; last-16-finishers run the conv epilogue.
// Register-lean main phase: Phase A streams (no value registers kept); Phases C/D
// reload qualifying chunks from global (L1-resident lines, ~39cyc hits).
// No gpu-scope fences (CCTL.IVALL flushes L1 on sm_103a); epilogue uses a
// monotone poll-sum barrier on the histogram row instead.
__global__ void __launch_bounds__(256, 6) fused_kernel(const float* __restrict__ in,
                                                       float* __restrict__ out) {
    const unsigned FULL = 0xFFFFFFFFu;
    int warp = (blockIdx.x * 256 + threadIdx.x) >> 5;   // row id [0, 16384)
    int lane = threadIdx.x & 31;
    int g = (warp & (TDIM - 1)) >> 6;

    const float4* p = (const float4*)(in + (size_t)warp * DDIM) + lane;

    // ---- Phase A: stream 32 elems/lane; keep only the 8 group maxes ----
    float gmax[8];
#pragma unroll
    for (int c = 0; c < 8; c++) {
        float4 t = p[c * 32];
        gmax[c] = fmaxf(fmaxf(t.x, t.y), fmaxf(t.z, t.w));
    }
    float lmax = gmax[0];
#pragma unroll
    for (int c = 1; c < 8; c++) lmax = fmaxf(lmax, gmax[c]);

    // ---- Phase B: tau = 5th-largest of 32 lane-maxes (<= row's 5th value) ----
    unsigned s = sortable(lmax);
    unsigned tau_s = 0;
#pragma unroll
    for (int r = 0; r < 5; r++) {
        unsigned best = __reduce_max_sync(FULL, s);
        tau_s = best;
        int w = __ffs(__ballot_sync(FULL, s == best)) - 1;
        if (lane == w) s = 0;
    }
    float tauf = unsortable(tau_s);

    // ---- Phase C: candidates >= tau (reload qualifying chunks from L1) ----
    // key = (sortable(value) << 10) | (1023 - idx)
    unsigned long long ck = 0;
    int cnt = 0;
#pragma unroll
    for (int c = 0; c < 8; c++) {
        if (gmax[c] >= tauf) {
            float4 t = p[c * 32];
#pragma unroll
            for (int j = 0; j < 4; j++) {
                float f = comp4(t, j);
                if (f >= tauf) {
                    int idx = ((lane + c * 32) << 2) + j;
                    unsigned long long key =
                        ((unsigned long long)sortable(f) << 10) | (unsigned)(1023 - idx);
                    cnt++;
                    if (key > ck) ck = key;
                }
            }
        }
    }

    // ---- Phase D: exact top-5 extraction (value, lowest-index tie-break) ----
    int myidx = 0;
#pragma unroll
    for (int r = 0; r < 5; r++) {
        unsigned hi = (unsigned)(ck >> 10);
        unsigned bestv = __reduce_max_sync(FULL, hi);
        unsigned myinv = (unsigned)(ck & 1023u);
        unsigned inv_c = (hi == bestv) ? myinv : 0u;
        unsigned besti = __reduce_max_sync(FULL, inv_c);
        if (lane == r) myidx = 1023 - (int)besti;
        if (hi == bestv && myinv == besti) {          // unique winner lane
            cnt--;
            if (cnt > 0) {
                unsigned long long ub = ck;           // next best strictly below ub
                unsigned long long nk = 0;
#pragma unroll
                for (int c = 0; c < 8; c++) {
                    if (gmax[c] >= tauf) {
                        float4 t = p[c * 32];
#pragma unroll
                        for (int j = 0; j < 4; j++) {
                            float f = comp4(t, j);
                            if (f >= tauf) {
                                int idx = ((lane + c * 32) << 2) + j;
                                unsigned long long key =
                                    ((unsigned long long)sortable(f) << 10) |
                                    (unsigned)(1023 - idx);
                                if (key < ub && key > nk) nk = key;
                            }
                        }
                    }
                }
                ck = nk;
            } else {
                ck = 0;
            }
        }
    }

    if (lane < 5) atomicAdd(&g_counts[g * DDIM + myidx], 1);

    // ================= epilogue: last 16 ticket-takers run the conv =================
    __shared__ int s_ticket;
    __syncthreads();
    if (threadIdx.x == 0) s_ticket = atomicAdd(&g_done, 1);
    __syncthreads();
    int ticket = s_ticket;
    if (ticket < NBLOCKS - BATCH) return;

    if (ticket == NBLOCKS - 1 && threadIdx.x == 0) g_done = 0;  // replay reset (all increments done)
    int row = ticket - (NBLOCKS - BATCH);
    int tid = threadIdx.x;

    __shared__ float srow[DDIM + 2 * RADIUS];
    __shared__ float w[2 * RADIUS + 1];
    __shared__ int wsum[8];
    __shared__ int s_sum;

    if (tid < 2 * RADIUS + 1) {
        int k = tid - RADIUS;
        w[tid] = 0.19947114020071635f * expf(-0.125f * (float)(k * k));
    }
    if (tid < RADIUS) { srow[tid] = 0.0f; srow[DDIM + RADIUS + tid] = 0.0f; }

    // Poll-sum barrier: monotone counts + matching total == consistent final snapshot.
    while (true) {
        int part = 0;
#pragma unroll
        for (int i = 0; i < 4; i++) {
            int d = tid * 4 + i;
            int val = __ldcg(&g_counts[row * DDIM + d]);   // L2-coherent, bypass L1
            srow[d + RADIUS] = (float)val;
            part += val;
        }
#pragma unroll
        for (int off = 16; off; off >>= 1) part += __shfl_xor_sync(FULL, part, off);
        if ((tid & 31) == 0) wsum[tid >> 5] = part;
        __syncthreads();
        if (tid == 0) {
            int t = 0;
#pragma unroll
            for (int i = 0; i < 8; i++) t += wsum[i];
            s_sum = t;
        }
        __syncthreads();
        if (s_sum == ROW_TOTAL) break;
        __nanosleep(200);
    }

    // Restore invariant for the next replay (all reads of this row are done block-wide).
#pragma unroll
    for (int i = 0; i < 4; i++) g_counts[row * DDIM + tid * 4 + i] = 0;

    // conv: out[row][d] = sum_k srow[d+k] * w[k]
    float4 acc;
#pragma unroll
    for (int i = 0; i < 4; i++) {
        int d = tid * 4 + i;
        float a = 0.0f;
#pragma unroll
        for (int k = 0; k < 2 * RADIUS + 1; k++) a += srow[d + k] * w[k];
        ((float*)&acc)[i] = a;
    }
    ((float4*)(out + row * DDIM))[tid] = acc;
}

extern "C" void kernel_launch(void* const* d_in, const int* in_sizes, int n_in,
                              void* d_out, int out_size) {
    const float* in = (const float*)d_in[0];
    float* out = (float*)d_out;
    fused_kernel<<<NBLOCKS, 256>>>(in, out);
}

// round 7
// speedup vs baseline: 1.1896x; 1.1896x over previous
#include <cuda_runtime.h>
#include <cuda_bf16.h>

#define BATCH  16
#define TDIM   1024
#define DDIM   1024
#define RADIUS 15

// Per-output-group histogram of top-5 index hits; g = t >> 6.
// Zero at module load; conv_kernel re-zeroes its own row after reading,
// so the invariant (zero at topk entry) holds on every graph replay.
__device__ int g_counts[BATCH * DDIM];

// Monotone float->unsigned bit mapping (order-preserving for non-NaN).
__device__ __forceinline__ unsigned sortable(float f) {
    unsigned u = __float_as_uint(f);
    return u ^ (((unsigned)((int)u >> 31)) | 0x80000000u);
}
__device__ __forceinline__ float unsortable(unsigned s) {
    unsigned u = (s & 0x80000000u) ? (s ^ 0x80000000u) : ~s;
    return __uint_as_float(u);
}
__device__ __forceinline__ float comp4(float4 v, int j) {
    return (j == 0) ? v.x : (j == 1) ? v.y : (j == 2) ? v.z : v.w;
}

// One warp per (b, t) row of 1024 floats. Register-resident row (v[8], MLP=8).
// min-blocks 5 caps regs at 51 -> 40 resident warps/SM for latency hiding.
__global__ void __launch_bounds__(256, 5) topk_hist_kernel(const float* __restrict__ in) {
    const unsigned FULL = 0xFFFFFFFFu;
    int warp = (blockIdx.x * 256 + threadIdx.x) >> 5;   // row id [0, 16384)
    int lane = threadIdx.x & 31;
    int g = (warp & (TDIM - 1)) >> 6;

    const float4* p = (const float4*)(in + (size_t)warp * DDIM) + lane;

    // ---- Phase A: 8 independent LDG.128 (kept live), branchless group maxes ----
    float4 v[8];
    float gmax[8];
#pragma unroll
    for (int c = 0; c < 8; c++) {
        v[c] = p[c * 32];
        gmax[c] = fmaxf(fmaxf(v[c].x, v[c].y), fmaxf(v[c].z, v[c].w));
    }
    float lmax = gmax[0];
#pragma unroll
    for (int c = 1; c < 8; c++) lmax = fmaxf(lmax, gmax[c]);

    // ---- Phase B: tau = 5th-largest of 32 lane-maxes (<= row's 5th value) ----
    unsigned s = sortable(lmax);
    unsigned tau_s = 0;
#pragma unroll
    for (int r = 0; r < 5; r++) {
        unsigned best = __reduce_max_sync(FULL, s);
        tau_s = best;
        int w = __ffs(__ballot_sync(FULL, s == best)) - 1;
        if (lane == w) s = 0;
    }
    float tauf = unsortable(tau_s);

    // ---- Phase C: candidates >= tau; per-lane best key + count ----
    // key = (sortable(value) << 10) | (1023 - idx): value-major, lowest-index-wins.
    unsigned long long ck = 0;
    int cnt = 0;
#pragma unroll
    for (int c = 0; c < 8; c++) {
        if (gmax[c] >= tauf) {
#pragma unroll
            for (int j = 0; j < 4; j++) {
                float f = comp4(v[c], j);
                if (f >= tauf) {
                    int idx = ((lane + c * 32) << 2) + j;
                    unsigned long long key =
                        ((unsigned long long)sortable(f) << 10) | (unsigned)(1023 - idx);
                    cnt++;
                    if (key > ck) ck = key;
                }
            }
        }
    }

    // ---- Phase D: exact top-5 extraction (value, lowest-index tie-break) ----
    int myidx = 0;
#pragma unroll
    for (int r = 0; r < 5; r++) {
        unsigned hi = (unsigned)(ck >> 10);
        unsigned bestv = __reduce_max_sync(FULL, hi);
        unsigned myinv = (unsigned)(ck & 1023u);
        unsigned inv_c = (hi == bestv) ? myinv : 0u;
        unsigned besti = __reduce_max_sync(FULL, inv_c);
        if (lane == r) myidx = 1023 - (int)besti;
        if (hi == bestv && myinv == besti) {          // unique winner lane
            cnt--;
            if (cnt > 0) {
                unsigned long long ub = ck;
                unsigned long long nk = 0;
#pragma unroll
                for (int c = 0; c < 8; c++) {
                    if (gmax[c] >= tauf) {
#pragma unroll
                        for (int j = 0; j < 4; j++) {
                            float f = comp4(v[c], j);
                            if (f >= tauf) {
                                int idx = ((lane + c * 32) << 2) + j;
                                unsigned long long key =
                                    ((unsigned long long)sortable(f) << 10) |
                                    (unsigned)(1023 - idx);
                                if (key < ub && key > nk) nk = key;
                            }
                        }
                    }
                }
                ck = nk;
            } else {
                ck = 0;
            }
        }
    }

    if (lane < 5) atomicAdd(&g_counts[g * DDIM + myidx], 1);
}

// out[g][d] = sum_k counts[g][m] * NORM * exp(-0.125*(d-m)^2), |d-m| <= 15.
// 16 blocks x 256 threads, 4 outputs/thread, int4 count loads, one barrier.
// Self-zeroes its own row (race-free: no cross-block halo) for the next replay.
__global__ void __launch_bounds__(256) conv_kernel(float* __restrict__ out) {
    __shared__ float srow[DDIM + 2 * RADIUS];
    __shared__ float w[2 * RADIUS + 1];
    int g = blockIdx.x;
    int tid = threadIdx.x;

    if (tid < 2 * RADIUS + 1) {
        int k = tid - RADIUS;
        w[tid] = 0.19947114020071635f * expf(-0.125f * (float)(k * k));
    }
    // 4 counts per thread via one LDG.128
    int4 c4 = ((const int4*)(g_counts + g * DDIM))[tid];
    srow[RADIUS + tid * 4 + 0] = (float)c4.x;
    srow[RADIUS + tid * 4 + 1] = (float)c4.y;
    srow[RADIUS + tid * 4 + 2] = (float)c4.z;
    srow[RADIUS + tid * 4 + 3] = (float)c4.w;
    if (tid < RADIUS) { srow[tid] = 0.0f; srow[DDIM + RADIUS + tid] = 0.0f; }
    __syncthreads();

    // restore invariant for next replay (after the barrier; block-local row)
    ((int4*)(g_counts + g * DDIM))[tid] = make_int4(0, 0, 0, 0);

    float4 acc;
#pragma unroll
    for (int i = 0; i < 4; i++) {
        int d = tid * 4 + i;
        float a = 0.0f;
#pragma unroll
        for (int k = 0; k < 2 * RADIUS + 1; k++) a += srow[d + k] * w[k];
        ((float*)&acc)[i] = a;
    }
    ((float4*)(out + g * DDIM))[tid] = acc;
}

extern "C" void kernel_launch(void* const* d_in, const int* in_sizes, int n_in,
                              void* d_out, int out_size) {
    const float* in = (const float*)d_in[0];
    float* out = (float*)d_out;

    topk_hist_kernel<<<2048, 256>>>(in);   // 1 warp per row
    conv_kernel<<<BATCH, 256>>>(out);
}